// round 9
// baseline (speedup 1.0000x reference)
#include <cuda_runtime.h>
#include <cuda_bf16.h>
#include <cstdint>

// Problem constants (fixed by the dataset)
#define N_NODES 100000
#define N_EDGES 600000
#define IN_C  128
#define HID_C 128
#define OUT_C 64

#define SCAN_BLK 1024
#define SCAN_NB  ((N_NODES + SCAN_BLK - 1) / SCAN_BLK)

// ===================== scratch (static device globals) ======================
__device__ float g_dinv[N_NODES];
__device__ int   g_cnt [N_NODES];          // in-degree (no self loop)
__device__ int   g_rs  [N_NODES];          // row start (exclusive prefix of cnt)
__device__ int   g_fill[N_NODES];          // fill cursor
__device__ int   g_bsum[SCAN_NB];          // scan block sums
__device__ int   g_csr_src[N_EDGES];       // src ids grouped by dst
__device__ float g_h1s [(size_t)N_NODES * HID_C];  // (x@W1) * dinv[row]
__device__ float g_a1  [(size_t)N_NODES * HID_C];  // relu-activated layer-1 out
__device__ float g_h2s [(size_t)N_NODES * OUT_C];  // (a1@W2) * dinv[row]

// Pre-swizzled transposed split weights: row n (output ch), 128 bf16 k's,
// 256 B/row, 16B-block XOR swizzle: blk' = blk ^ (n & 7).
__device__ __align__(128) unsigned char g_B1hi[HID_C * 256];   // 32768 B
__device__ __align__(128) unsigned char g_B1lo[HID_C * 256];
__device__ __align__(128) unsigned char g_B2hi[OUT_C * 256];   // 16384 B
__device__ __align__(128) unsigned char g_B2lo[OUT_C * 256];

__device__ __forceinline__ uint32_t sw_off(int row, int k) {
    return (uint32_t)row * 256u + ((((uint32_t)k >> 3) ^ ((uint32_t)row & 7u)) << 4)
         + ((uint32_t)k & 7u) * 2u;
}

__device__ __forceinline__ uint32_t smem_u32(const void* p) {
    uint32_t a;
    asm("{ .reg .u64 t; cvta.to.shared.u64 t, %1; cvt.u32.u64 %0, t; }" : "=r"(a) : "l"(p));
    return a;
}

__device__ __forceinline__ void ldsm_x4(uint32_t& r0, uint32_t& r1,
                                        uint32_t& r2, uint32_t& r3, uint32_t addr) {
    asm volatile("ldmatrix.sync.aligned.m8n8.x4.shared.b16 {%0,%1,%2,%3}, [%4];"
                 : "=r"(r0), "=r"(r1), "=r"(r2), "=r"(r3) : "r"(addr));
}

__device__ __forceinline__ void mma_bf16(float& c0, float& c1, float& c2, float& c3,
                                         uint32_t a0, uint32_t a1, uint32_t a2, uint32_t a3,
                                         uint32_t b0, uint32_t b1) {
    asm volatile("mma.sync.aligned.m16n8k16.row.col.f32.bf16.bf16.f32 "
                 "{%0,%1,%2,%3}, {%4,%5,%6,%7}, {%8,%9}, {%0,%1,%2,%3};"
                 : "+f"(c0), "+f"(c1), "+f"(c2), "+f"(c3)
                 : "r"(a0), "r"(a1), "r"(a2), "r"(a3), "r"(b0), "r"(b1));
}

__device__ __forceinline__ void split2(float a, float b, uint32_t& hi, uint32_t& lo) {
    __nv_bfloat16 ha = __float2bfloat16(a);
    __nv_bfloat16 hb = __float2bfloat16(b);
    __nv_bfloat162 h = __halves2bfloat162(ha, hb);
    __nv_bfloat162 l = __halves2bfloat162(__float2bfloat16(a - __bfloat162float(ha)),
                                          __float2bfloat16(b - __bfloat162float(hb)));
    hi = *(uint32_t*)&h;
    lo = *(uint32_t*)&l;
}

// ============ prep: weight transpose/split/swizzle + zero cnt/fill ==========
__global__ void prep_kernel(const float* __restrict__ W1,
                            const float* __restrict__ W2, int n) {
    const int i = blockIdx.x * blockDim.x + threadIdx.x;
    if (i < n) { g_cnt[i] = 0; g_fill[i] = 0; }
    if (i < IN_C * HID_C) {
        const int k = i >> 7;        // input channel
        const int nn = i & 127;      // output channel
        const float v = W1[k * HID_C + nn];
        const __nv_bfloat16 h = __float2bfloat16(v);
        const __nv_bfloat16 l = __float2bfloat16(v - __bfloat162float(h));
        const uint32_t off = sw_off(nn, k);
        *(__nv_bfloat16*)(g_B1hi + off) = h;
        *(__nv_bfloat16*)(g_B1lo + off) = l;
    } else if (i < IN_C * HID_C + HID_C * OUT_C) {
        const int j = i - IN_C * HID_C;
        const int k = j >> 6;
        const int nn = j & 63;
        const float v = W2[k * OUT_C + nn];
        const __nv_bfloat16 h = __float2bfloat16(v);
        const __nv_bfloat16 l = __float2bfloat16(v - __bfloat162float(h));
        const uint32_t off = sw_off(nn, k);
        *(__nv_bfloat16*)(g_B2hi + off) = h;
        *(__nv_bfloat16*)(g_B2lo + off) = l;
    }
}

// ===================== CSR build ============================================
__global__ void count_kernel(const int* __restrict__ dst, int E) {
    int e = blockIdx.x * blockDim.x + threadIdx.x;
    if (e < E) atomicAdd(&g_cnt[dst[e]], 1);
}

// per-block exclusive scan of g_cnt -> g_rs (partial), block sums -> g_bsum,
// plus dinv = rsqrt(cnt + 1) fused.
__global__ void scan1_kernel(int n) {
    __shared__ int sh[SCAN_BLK];
    const int i = blockIdx.x * SCAN_BLK + threadIdx.x;
    const int v = (i < n) ? g_cnt[i] : 0;
    if (i < n) g_dinv[i] = rsqrtf((float)(v + 1));
    sh[threadIdx.x] = v;
    __syncthreads();
    for (int off = 1; off < SCAN_BLK; off <<= 1) {
        int t = (threadIdx.x >= off) ? sh[threadIdx.x - off] : 0;
        __syncthreads();
        sh[threadIdx.x] += t;
        __syncthreads();
    }
    if (i < n) g_rs[i] = sh[threadIdx.x] - v;  // exclusive (within block)
    if (threadIdx.x == SCAN_BLK - 1) g_bsum[blockIdx.x] = sh[threadIdx.x];
}

// scan3: each block computes its own offset = sum of bsum[0..blk) then adds.
__global__ void scan3_kernel(int n) {
    __shared__ int s_off;
    __shared__ int s_part[32];
    const int t = threadIdx.x;
    if (t < 128) {
        int v = (t < blockIdx.x && t < SCAN_NB) ? g_bsum[t] : 0;
#pragma unroll
        for (int o = 16; o > 0; o >>= 1)
            v += __shfl_down_sync(0xFFFFFFFF, v, o);
        if ((t & 31) == 0) s_part[t >> 5] = v;
    }
    __syncthreads();
    if (t == 0) s_off = s_part[0] + s_part[1] + s_part[2] + s_part[3];
    __syncthreads();
    const int i = blockIdx.x * SCAN_BLK + t;
    if (i < n) g_rs[i] += s_off;
}

__global__ void fill_kernel(const int* __restrict__ src,
                            const int* __restrict__ dst, int E) {
    int e = blockIdx.x * blockDim.x + threadIdx.x;
    if (e < E) {
        const int d = dst[e];
        const int pos = g_rs[d] + atomicAdd(&g_fill[d], 1);
        g_csr_src[pos] = src[e];
    }
}

// ===================== GEMM core (warp mma, bf16 split, 3 terms) ============
// 256 threads = 8 warps, warp grid 4(M) x 2(N). M_TILE = 128 rows.
// NT = n8 tiles per warp (8 for N=128, 4 for N=64).
template <int NC, int NT>
__device__ __forceinline__ void gemm_compute_epilogue(
    uint32_t sA_hi, uint32_t sA_lo, uint32_t sB_hi, uint32_t sB_lo,
    int block_row, int n_nodes, float* __restrict__ gh)
{
    const int tid = threadIdx.x;
    const int wid = tid >> 5;
    const int l   = tid & 31;
    const int mw  = wid >> 1;
    const int nw  = wid & 1;
    const int mbase = mw * 32;
    const int nbase = nw * (NT * 8);
    const int tg = l >> 2;
    const int tp = l & 3;

    float acc[2][NT][4];
#pragma unroll
    for (int mt = 0; mt < 2; mt++)
#pragma unroll
        for (int nt = 0; nt < NT; nt++)
#pragma unroll
            for (int c = 0; c < 4; c++) acc[mt][nt][c] = 0.0f;

    const int a_row_in = l & 15;
    const int a_kb_add = l >> 4;
    const int b_nrow   = l & 7;
    const int b_nt_add = l >> 4;
    const int b_kb_add = (l >> 3) & 1;

#pragma unroll
    for (int ks = 0; ks < 8; ks++) {
        const int kb0 = ks * 2;
        uint32_t ah[2][4], al[2][4];
#pragma unroll
        for (int mt = 0; mt < 2; mt++) {
            const int row = mbase + mt * 16 + a_row_in;
            const uint32_t off = (uint32_t)row * 256u
                + ((uint32_t)((kb0 + a_kb_add) ^ (row & 7)) << 4);
            ldsm_x4(ah[mt][0], ah[mt][1], ah[mt][2], ah[mt][3], sA_hi + off);
            ldsm_x4(al[mt][0], al[mt][1], al[mt][2], al[mt][3], sA_lo + off);
        }
        uint32_t bh[NT][2], bl[NT][2];
#pragma unroll
        for (int j = 0; j < NT / 2; j++) {
            const int n = nbase + (2 * j + b_nt_add) * 8 + b_nrow;
            const uint32_t off = (uint32_t)n * 256u
                + ((uint32_t)((kb0 + b_kb_add) ^ (n & 7)) << 4);
            ldsm_x4(bh[2*j][0], bh[2*j][1], bh[2*j+1][0], bh[2*j+1][1], sB_hi + off);
            ldsm_x4(bl[2*j][0], bl[2*j][1], bl[2*j+1][0], bl[2*j+1][1], sB_lo + off);
        }
#pragma unroll
        for (int mt = 0; mt < 2; mt++)
#pragma unroll
            for (int nt = 0; nt < NT; nt++) {
                mma_bf16(acc[mt][nt][0], acc[mt][nt][1], acc[mt][nt][2], acc[mt][nt][3],
                         ah[mt][0], ah[mt][1], ah[mt][2], ah[mt][3], bh[nt][0], bh[nt][1]);
                mma_bf16(acc[mt][nt][0], acc[mt][nt][1], acc[mt][nt][2], acc[mt][nt][3],
                         al[mt][0], al[mt][1], al[mt][2], al[mt][3], bh[nt][0], bh[nt][1]);
                mma_bf16(acc[mt][nt][0], acc[mt][nt][1], acc[mt][nt][2], acc[mt][nt][3],
                         ah[mt][0], ah[mt][1], ah[mt][2], ah[mt][3], bl[nt][0], bl[nt][1]);
            }
    }

    // Epilogue: gh = acc * dinv[row]
#pragma unroll
    for (int mt = 0; mt < 2; mt++) {
        const int r0 = block_row + mbase + mt * 16 + tg;
        const int r1 = r0 + 8;
        const bool v0 = r0 < n_nodes;
        const bool v1 = r1 < n_nodes;
        const float d0 = v0 ? g_dinv[r0] : 0.0f;
        const float d1 = v1 ? g_dinv[r1] : 0.0f;
#pragma unroll
        for (int nt = 0; nt < NT; nt++) {
            const int col = nbase + nt * 8 + tp * 2;
            if (v0) {
                float2 o; o.x = acc[mt][nt][0] * d0; o.y = acc[mt][nt][1] * d0;
                *(float2*)&gh[(size_t)r0 * NC + col] = o;
            }
            if (v1) {
                float2 o; o.x = acc[mt][nt][2] * d1; o.y = acc[mt][nt][3] * d1;
                *(float2*)&gh[(size_t)r1 * NC + col] = o;
            }
        }
    }
}

// ===================== GEMM1: h1s = (x@W1)*dinv (M_TILE=128) ================
__global__ __launch_bounds__(256) void gemm1_kernel(const float* __restrict__ x,
                                                    int n_nodes) {
    extern __shared__ char smem[];
    const uint32_t sbase = smem_u32(smem);
    const uint32_t sA_hi = sbase;
    const uint32_t sA_lo = sbase + 32768;
    const uint32_t sB_hi = sbase + 65536;
    const uint32_t sB_lo = sbase + 98304;

    const int tid = threadIdx.x;
    const int block_row = blockIdx.x * 128;

    {
        const uint4* sh = (const uint4*)g_B1hi;
        const uint4* sl = (const uint4*)g_B1lo;
        uint4* dh = (uint4*)(smem + 65536);
        uint4* dl = (uint4*)(smem + 98304);
#pragma unroll
        for (int i = tid; i < 2048; i += 256) { dh[i] = sh[i]; dl[i] = sl[i]; }
    }

    {
        const int l = tid & 31;
        const int w = tid >> 5;
        uint2* Ah = (uint2*)smem;
        uint2* Al = (uint2*)(smem + 32768);
#pragma unroll
        for (int p = 0; p < 16; p++) {
            const int r = w + 8 * p;
            const int grow = block_row + r;
            float4 v = make_float4(0.f, 0.f, 0.f, 0.f);
            if (grow < n_nodes) v = *(const float4*)&x[(size_t)grow * IN_C + 4 * l];
            uint2 h, lo;
            split2(v.x, v.y, h.x, lo.x);
            split2(v.z, v.w, h.y, lo.y);
            const uint32_t off = ((uint32_t)r * 256u
                + ((uint32_t)((l >> 1) ^ (r & 7)) << 4) + (uint32_t)(l & 1) * 8u) >> 3;
            Ah[off] = h;
            Al[off] = lo;
        }
    }
    __syncthreads();

    gemm_compute_epilogue<HID_C, 8>(sA_hi, sA_lo, sB_hi, sB_lo,
                                    block_row, n_nodes, g_h1s);
}

// ===================== AGG1: a1 = relu(dinv*(h1s[d] + sum_in h1s[s]) + b1) ==
__global__ __launch_bounds__(256) void agg1_kernel(const float* __restrict__ b1,
                                                   int n_nodes) {
    const int gid  = blockIdx.x * blockDim.x + threadIdx.x;
    const int node = gid >> 5;
    if (node >= n_nodes) return;
    const int lane = gid & 31;

    const int beg = g_rs[node];
    const int end = beg + g_cnt[node];

    float4 a0 = *(const float4*)&g_h1s[(size_t)node * HID_C + lane * 4];  // self
    float4 a1v = make_float4(0.f, 0.f, 0.f, 0.f);
    float4 a2 = make_float4(0.f, 0.f, 0.f, 0.f);
    float4 a3 = make_float4(0.f, 0.f, 0.f, 0.f);

    int e = beg;
    for (; e + 3 < end; e += 4) {
        const int s0 = __ldg(&g_csr_src[e]);
        const int s1 = __ldg(&g_csr_src[e + 1]);
        const int s2 = __ldg(&g_csr_src[e + 2]);
        const int s3 = __ldg(&g_csr_src[e + 3]);
        const float4 v0 = *(const float4*)&g_h1s[(size_t)s0 * HID_C + lane * 4];
        const float4 v1 = *(const float4*)&g_h1s[(size_t)s1 * HID_C + lane * 4];
        const float4 v2 = *(const float4*)&g_h1s[(size_t)s2 * HID_C + lane * 4];
        const float4 v3 = *(const float4*)&g_h1s[(size_t)s3 * HID_C + lane * 4];
        a0.x += v0.x; a0.y += v0.y; a0.z += v0.z; a0.w += v0.w;
        a1v.x += v1.x; a1v.y += v1.y; a1v.z += v1.z; a1v.w += v1.w;
        a2.x += v2.x; a2.y += v2.y; a2.z += v2.z; a2.w += v2.w;
        a3.x += v3.x; a3.y += v3.y; a3.z += v3.z; a3.w += v3.w;
    }
    for (; e < end; e++) {
        const int s0 = __ldg(&g_csr_src[e]);
        const float4 v0 = *(const float4*)&g_h1s[(size_t)s0 * HID_C + lane * 4];
        a0.x += v0.x; a0.y += v0.y; a0.z += v0.z; a0.w += v0.w;
    }
    a0.x += a1v.x + a2.x + a3.x;
    a0.y += a1v.y + a2.y + a3.y;
    a0.z += a1v.z + a2.z + a3.z;
    a0.w += a1v.w + a2.w + a3.w;

    const float di = g_dinv[node];
    const float4 b = *(const float4*)&b1[lane * 4];
    float4 o;
    o.x = fmaxf(di * a0.x + b.x, 0.0f);
    o.y = fmaxf(di * a0.y + b.y, 0.0f);
    o.z = fmaxf(di * a0.z + b.z, 0.0f);
    o.w = fmaxf(di * a0.w + b.w, 0.0f);
    *(float4*)&g_a1[(size_t)node * HID_C + lane * 4] = o;
}

// ===================== GEMM2: h2s = (a1@W2)*dinv (M_TILE=128) ===============
__global__ __launch_bounds__(256) void gemm2_kernel(int n_nodes) {
    extern __shared__ char smem[];
    const uint32_t sbase = smem_u32(smem);
    const uint32_t sA_hi = sbase;
    const uint32_t sA_lo = sbase + 32768;
    const uint32_t sB_hi = sbase + 65536;
    const uint32_t sB_lo = sbase + 81920;

    const int tid = threadIdx.x;
    const int block_row = blockIdx.x * 128;

    {
        const uint4* sh = (const uint4*)g_B2hi;
        const uint4* sl = (const uint4*)g_B2lo;
        uint4* dh = (uint4*)(smem + 65536);
        uint4* dl = (uint4*)(smem + 81920);
#pragma unroll
        for (int i = tid; i < 1024; i += 256) { dh[i] = sh[i]; dl[i] = sl[i]; }
    }

    {
        const int l = tid & 31;
        const int w = tid >> 5;
        uint2* Ah = (uint2*)smem;
        uint2* Al = (uint2*)(smem + 32768);
#pragma unroll
        for (int p = 0; p < 16; p++) {
            const int r = w + 8 * p;
            const int grow = block_row + r;
            float4 a = make_float4(0.f, 0.f, 0.f, 0.f);
            if (grow < n_nodes)
                a = *(const float4*)&g_a1[(size_t)grow * HID_C + 4 * l];
            uint2 h2, lo;
            split2(a.x, a.y, h2.x, lo.x);
            split2(a.z, a.w, h2.y, lo.y);
            const uint32_t off = ((uint32_t)r * 256u
                + ((uint32_t)((l >> 1) ^ (r & 7)) << 4) + (uint32_t)(l & 1) * 8u) >> 3;
            Ah[off] = h2;
            Al[off] = lo;
        }
    }
    __syncthreads();

    gemm_compute_epilogue<OUT_C, 4>(sA_hi, sA_lo, sB_hi, sB_lo,
                                    block_row, n_nodes, g_h2s);
}

// ===================== AGG2: out = dinv*(h2s[d] + sum_in h2s[s]) + b2 =======
__global__ __launch_bounds__(256) void agg2_kernel(const float* __restrict__ b2,
                                                   float* __restrict__ out,
                                                   int n_nodes) {
    const int gid  = blockIdx.x * blockDim.x + threadIdx.x;
    const int node = gid >> 4;
    if (node >= n_nodes) return;
    const int lane = gid & 15;

    const int beg = g_rs[node];
    const int end = beg + g_cnt[node];

    float4 a0 = *(const float4*)&g_h2s[(size_t)node * OUT_C + lane * 4];  // self
    float4 a1v = make_float4(0.f, 0.f, 0.f, 0.f);
    float4 a2 = make_float4(0.f, 0.f, 0.f, 0.f);
    float4 a3 = make_float4(0.f, 0.f, 0.f, 0.f);

    int e = beg;
    for (; e + 3 < end; e += 4) {
        const int s0 = __ldg(&g_csr_src[e]);
        const int s1 = __ldg(&g_csr_src[e + 1]);
        const int s2 = __ldg(&g_csr_src[e + 2]);
        const int s3 = __ldg(&g_csr_src[e + 3]);
        const float4 v0 = *(const float4*)&g_h2s[(size_t)s0 * OUT_C + lane * 4];
        const float4 v1 = *(const float4*)&g_h2s[(size_t)s1 * OUT_C + lane * 4];
        const float4 v2 = *(const float4*)&g_h2s[(size_t)s2 * OUT_C + lane * 4];
        const float4 v3 = *(const float4*)&g_h2s[(size_t)s3 * OUT_C + lane * 4];
        a0.x += v0.x; a0.y += v0.y; a0.z += v0.z; a0.w += v0.w;
        a1v.x += v1.x; a1v.y += v1.y; a1v.z += v1.z; a1v.w += v1.w;
        a2.x += v2.x; a2.y += v2.y; a2.z += v2.z; a2.w += v2.w;
        a3.x += v3.x; a3.y += v3.y; a3.z += v3.z; a3.w += v3.w;
    }
    for (; e < end; e++) {
        const int s0 = __ldg(&g_csr_src[e]);
        const float4 v0 = *(const float4*)&g_h2s[(size_t)s0 * OUT_C + lane * 4];
        a0.x += v0.x; a0.y += v0.y; a0.z += v0.z; a0.w += v0.w;
    }
    a0.x += a1v.x + a2.x + a3.x;
    a0.y += a1v.y + a2.y + a3.y;
    a0.z += a1v.z + a2.z + a3.z;
    a0.w += a1v.w + a2.w + a3.w;

    const float di = g_dinv[node];
    const float4 b = *(const float4*)&b2[lane * 4];
    float4 o;
    o.x = di * a0.x + b.x;
    o.y = di * a0.y + b.y;
    o.z = di * a0.z + b.z;
    o.w = di * a0.w + b.w;
    *(float4*)&out[(size_t)node * OUT_C + lane * 4] = o;
}

// ===================== launch ===============================================
extern "C" void kernel_launch(void* const* d_in, const int* in_sizes, int n_in,
                              void* d_out, int out_size) {
    const float* x   = (const float*)d_in[0];
    const float* W1  = (const float*)d_in[1];
    const float* b1  = (const float*)d_in[2];
    const float* W2  = (const float*)d_in[3];
    const float* b2  = (const float*)d_in[4];
    const int*   src = (const int*)  d_in[5];
    const int*   dst = (const int*)  d_in[6];
    float*       out = (float*)d_out;

    const int n = in_sizes[0] / IN_C;   // 100000
    const int E = in_sizes[5];          // 600000

    static bool attr_done = false;
    if (!attr_done) {
        cudaFuncSetAttribute(gemm1_kernel,
                             cudaFuncAttributeMaxDynamicSharedMemorySize, 131072);
        cudaFuncSetAttribute(gemm2_kernel,
                             cudaFuncAttributeMaxDynamicSharedMemorySize, 98304);
        attr_done = true;
    }

    // weight prep + zero + CSR build + dinv
    prep_kernel<<<(n + 255) / 256, 256>>>(W1, W2, n);
    count_kernel<<<(E + 255) / 256, 256>>>(dst, E);
    scan1_kernel<<<SCAN_NB, SCAN_BLK>>>(n);
    scan3_kernel<<<SCAN_NB, SCAN_BLK>>>(n);
    fill_kernel<<<(E + 255) / 256, 256>>>(src, dst, E);

    const int tiles = (n + 127) / 128;

    // layer 1
    gemm1_kernel<<<tiles, 256, 131072>>>(x, n);
    {
        long long threads = (long long)n * 32;
        agg1_kernel<<<(int)((threads + 255) / 256), 256>>>(b1, n);
    }

    // layer 2
    gemm2_kernel<<<tiles, 256, 98304>>>(n);
    {
        long long threads = (long long)n * 16;
        agg2_kernel<<<(int)((threads + 255) / 256), 256>>>(b2, out, n);
    }
}

// round 11
// speedup vs baseline: 1.1684x; 1.1684x over previous
#include <cuda_runtime.h>
#include <cuda_bf16.h>
#include <cstdint>

// Problem constants (fixed by the dataset)
#define N_NODES 100000
#define N_EDGES 600000
#define IN_C  128
#define HID_C 128
#define OUT_C 64

#define SCAN_BLK 1024
#define SCAN_NB  ((N_NODES + SCAN_BLK - 1) / SCAN_BLK)

// ===================== scratch (static device globals) ======================
__device__ float g_dinv[N_NODES];
__device__ int   g_cnt [N_NODES];          // in-degree (no self loop)
__device__ int   g_rs  [N_NODES];          // row start (exclusive prefix of cnt)
__device__ int   g_fill[N_NODES];          // fill cursor
__device__ int   g_bsum[SCAN_NB];          // scan block sums
__device__ int   g_csr_src[N_EDGES];       // src ids grouped by dst
__device__ float g_h1  [(size_t)N_NODES * HID_C];  // x@W1 (UNSCALED)
__device__ float g_a1  [(size_t)N_NODES * HID_C];  // relu-activated layer-1 out
__device__ float g_h2s [(size_t)N_NODES * OUT_C];  // (a1@W2) * dinv[row]

// Pre-swizzled transposed split weights: row n (output ch), 128 bf16 k's,
// 256 B/row, 16B-block XOR swizzle: blk' = blk ^ (n & 7).
__device__ __align__(128) unsigned char g_B1hi[HID_C * 256];   // 32768 B
__device__ __align__(128) unsigned char g_B1lo[HID_C * 256];
__device__ __align__(128) unsigned char g_B2hi[OUT_C * 256];   // 16384 B
__device__ __align__(128) unsigned char g_B2lo[OUT_C * 256];

__device__ __forceinline__ uint32_t sw_off(int row, int k) {
    return (uint32_t)row * 256u + ((((uint32_t)k >> 3) ^ ((uint32_t)row & 7u)) << 4)
         + ((uint32_t)k & 7u) * 2u;
}

__device__ __forceinline__ uint32_t smem_u32(const void* p) {
    uint32_t a;
    asm("{ .reg .u64 t; cvta.to.shared.u64 t, %1; cvt.u32.u64 %0, t; }" : "=r"(a) : "l"(p));
    return a;
}

__device__ __forceinline__ void ldsm_x4(uint32_t& r0, uint32_t& r1,
                                        uint32_t& r2, uint32_t& r3, uint32_t addr) {
    asm volatile("ldmatrix.sync.aligned.m8n8.x4.shared.b16 {%0,%1,%2,%3}, [%4];"
                 : "=r"(r0), "=r"(r1), "=r"(r2), "=r"(r3) : "r"(addr));
}

__device__ __forceinline__ void mma_bf16(float& c0, float& c1, float& c2, float& c3,
                                         uint32_t a0, uint32_t a1, uint32_t a2, uint32_t a3,
                                         uint32_t b0, uint32_t b1) {
    asm volatile("mma.sync.aligned.m16n8k16.row.col.f32.bf16.bf16.f32 "
                 "{%0,%1,%2,%3}, {%4,%5,%6,%7}, {%8,%9}, {%0,%1,%2,%3};"
                 : "+f"(c0), "+f"(c1), "+f"(c2), "+f"(c3)
                 : "r"(a0), "r"(a1), "r"(a2), "r"(a3), "r"(b0), "r"(b1));
}

__device__ __forceinline__ void split2(float a, float b, uint32_t& hi, uint32_t& lo) {
    __nv_bfloat16 ha = __float2bfloat16(a);
    __nv_bfloat16 hb = __float2bfloat16(b);
    __nv_bfloat162 h = __halves2bfloat162(ha, hb);
    __nv_bfloat162 l = __halves2bfloat162(__float2bfloat16(a - __bfloat162float(ha)),
                                          __float2bfloat16(b - __bfloat162float(hb)));
    hi = *(uint32_t*)&h;
    lo = *(uint32_t*)&l;
}

// ============ prep_w: weight transpose/split/swizzle (main stream) ==========
__global__ void prep_w_kernel(const float* __restrict__ W1,
                              const float* __restrict__ W2) {
    const int i = blockIdx.x * blockDim.x + threadIdx.x;
    if (i < IN_C * HID_C) {
        const int k = i >> 7;        // input channel
        const int nn = i & 127;      // output channel
        const float v = W1[k * HID_C + nn];
        const __nv_bfloat16 h = __float2bfloat16(v);
        const __nv_bfloat16 l = __float2bfloat16(v - __bfloat162float(h));
        const uint32_t off = sw_off(nn, k);
        *(__nv_bfloat16*)(g_B1hi + off) = h;
        *(__nv_bfloat16*)(g_B1lo + off) = l;
    } else if (i < IN_C * HID_C + HID_C * OUT_C) {
        const int j = i - IN_C * HID_C;
        const int k = j >> 6;
        const int nn = j & 63;
        const float v = W2[k * OUT_C + nn];
        const __nv_bfloat16 h = __float2bfloat16(v);
        const __nv_bfloat16 l = __float2bfloat16(v - __bfloat162float(h));
        const uint32_t off = sw_off(nn, k);
        *(__nv_bfloat16*)(g_B2hi + off) = h;
        *(__nv_bfloat16*)(g_B2lo + off) = l;
    }
}

// ===================== CSR build (side stream) ==============================
__global__ void zero_kernel(int n) {
    int i = blockIdx.x * blockDim.x + threadIdx.x;
    if (i < n) { g_cnt[i] = 0; g_fill[i] = 0; }
}

__global__ void count_kernel(const int* __restrict__ dst, int E) {
    int e = blockIdx.x * blockDim.x + threadIdx.x;
    if (e < E) atomicAdd(&g_cnt[dst[e]], 1);
}

// per-block exclusive scan of g_cnt -> g_rs (partial), block sums -> g_bsum,
// plus dinv = rsqrt(cnt + 1) fused.
__global__ void scan1_kernel(int n) {
    __shared__ int sh[SCAN_BLK];
    const int i = blockIdx.x * SCAN_BLK + threadIdx.x;
    const int v = (i < n) ? g_cnt[i] : 0;
    if (i < n) g_dinv[i] = rsqrtf((float)(v + 1));
    sh[threadIdx.x] = v;
    __syncthreads();
    for (int off = 1; off < SCAN_BLK; off <<= 1) {
        int t = (threadIdx.x >= off) ? sh[threadIdx.x - off] : 0;
        __syncthreads();
        sh[threadIdx.x] += t;
        __syncthreads();
    }
    if (i < n) g_rs[i] = sh[threadIdx.x] - v;  // exclusive (within block)
    if (threadIdx.x == SCAN_BLK - 1) g_bsum[blockIdx.x] = sh[threadIdx.x];
}

// scan3: each block computes its own offset = sum of bsum[0..blk) then adds.
__global__ void scan3_kernel(int n) {
    __shared__ int s_off;
    __shared__ int s_part[32];
    const int t = threadIdx.x;
    if (t < 128) {
        int v = (t < blockIdx.x && t < SCAN_NB) ? g_bsum[t] : 0;
#pragma unroll
        for (int o = 16; o > 0; o >>= 1)
            v += __shfl_down_sync(0xFFFFFFFF, v, o);
        if ((t & 31) == 0) s_part[t >> 5] = v;
    }
    __syncthreads();
    if (t == 0) s_off = s_part[0] + s_part[1] + s_part[2] + s_part[3];
    __syncthreads();
    const int i = blockIdx.x * SCAN_BLK + t;
    if (i < n) g_rs[i] += s_off;
}

__global__ void fill_kernel(const int* __restrict__ src,
                            const int* __restrict__ dst, int E) {
    int e = blockIdx.x * blockDim.x + threadIdx.x;
    if (e < E) {
        const int d = dst[e];
        const int pos = g_rs[d] + atomicAdd(&g_fill[d], 1);
        g_csr_src[pos] = src[e];
    }
}

// ===================== GEMM core (warp mma, bf16 split, 3 terms) ============
// 256 threads = 8 warps, warp grid 4(M) x 2(N). M_TILE = 128 rows.
// NT = n8 tiles per warp (8 for N=128, 4 for N=64).
// SCALE: multiply output rows by g_dinv[row] (gemm2 only).
template <int NC, int NT, bool SCALE>
__device__ __forceinline__ void gemm_compute_epilogue(
    uint32_t sA_hi, uint32_t sA_lo, uint32_t sB_hi, uint32_t sB_lo,
    int block_row, int n_nodes, float* __restrict__ gh)
{
    const int tid = threadIdx.x;
    const int wid = tid >> 5;
    const int l   = tid & 31;
    const int mw  = wid >> 1;
    const int nw  = wid & 1;
    const int mbase = mw * 32;
    const int nbase = nw * (NT * 8);
    const int tg = l >> 2;
    const int tp = l & 3;

    float acc[2][NT][4];
#pragma unroll
    for (int mt = 0; mt < 2; mt++)
#pragma unroll
        for (int nt = 0; nt < NT; nt++)
#pragma unroll
            for (int c = 0; c < 4; c++) acc[mt][nt][c] = 0.0f;

    const int a_row_in = l & 15;
    const int a_kb_add = l >> 4;
    const int b_nrow   = l & 7;
    const int b_nt_add = l >> 4;
    const int b_kb_add = (l >> 3) & 1;

#pragma unroll
    for (int ks = 0; ks < 8; ks++) {
        const int kb0 = ks * 2;
        uint32_t ah[2][4], al[2][4];
#pragma unroll
        for (int mt = 0; mt < 2; mt++) {
            const int row = mbase + mt * 16 + a_row_in;
            const uint32_t off = (uint32_t)row * 256u
                + ((uint32_t)((kb0 + a_kb_add) ^ (row & 7)) << 4);
            ldsm_x4(ah[mt][0], ah[mt][1], ah[mt][2], ah[mt][3], sA_hi + off);
            ldsm_x4(al[mt][0], al[mt][1], al[mt][2], al[mt][3], sA_lo + off);
        }
        uint32_t bh[NT][2], bl[NT][2];
#pragma unroll
        for (int j = 0; j < NT / 2; j++) {
            const int n = nbase + (2 * j + b_nt_add) * 8 + b_nrow;
            const uint32_t off = (uint32_t)n * 256u
                + ((uint32_t)((kb0 + b_kb_add) ^ (n & 7)) << 4);
            ldsm_x4(bh[2*j][0], bh[2*j][1], bh[2*j+1][0], bh[2*j+1][1], sB_hi + off);
            ldsm_x4(bl[2*j][0], bl[2*j][1], bl[2*j+1][0], bl[2*j+1][1], sB_lo + off);
        }
#pragma unroll
        for (int mt = 0; mt < 2; mt++)
#pragma unroll
            for (int nt = 0; nt < NT; nt++) {
                mma_bf16(acc[mt][nt][0], acc[mt][nt][1], acc[mt][nt][2], acc[mt][nt][3],
                         ah[mt][0], ah[mt][1], ah[mt][2], ah[mt][3], bh[nt][0], bh[nt][1]);
                mma_bf16(acc[mt][nt][0], acc[mt][nt][1], acc[mt][nt][2], acc[mt][nt][3],
                         al[mt][0], al[mt][1], al[mt][2], al[mt][3], bh[nt][0], bh[nt][1]);
                mma_bf16(acc[mt][nt][0], acc[mt][nt][1], acc[mt][nt][2], acc[mt][nt][3],
                         ah[mt][0], ah[mt][1], ah[mt][2], ah[mt][3], bl[nt][0], bl[nt][1]);
            }
    }

    // Epilogue
#pragma unroll
    for (int mt = 0; mt < 2; mt++) {
        const int r0 = block_row + mbase + mt * 16 + tg;
        const int r1 = r0 + 8;
        const bool v0 = r0 < n_nodes;
        const bool v1 = r1 < n_nodes;
        const float d0 = (SCALE && v0) ? g_dinv[r0] : 1.0f;
        const float d1 = (SCALE && v1) ? g_dinv[r1] : 1.0f;
#pragma unroll
        for (int nt = 0; nt < NT; nt++) {
            const int col = nbase + nt * 8 + tp * 2;
            if (v0) {
                float2 o; o.x = acc[mt][nt][0] * d0; o.y = acc[mt][nt][1] * d0;
                *(float2*)&gh[(size_t)r0 * NC + col] = o;
            }
            if (v1) {
                float2 o; o.x = acc[mt][nt][2] * d1; o.y = acc[mt][nt][3] * d1;
                *(float2*)&gh[(size_t)r1 * NC + col] = o;
            }
        }
    }
}

// ===================== GEMM1: h1 = x@W1 (UNSCALED, M_TILE=128) ==============
__global__ __launch_bounds__(256) void gemm1_kernel(const float* __restrict__ x,
                                                    int n_nodes) {
    extern __shared__ char smem[];
    const uint32_t sbase = smem_u32(smem);
    const uint32_t sA_hi = sbase;
    const uint32_t sA_lo = sbase + 32768;
    const uint32_t sB_hi = sbase + 65536;
    const uint32_t sB_lo = sbase + 98304;

    const int tid = threadIdx.x;
    const int block_row = blockIdx.x * 128;

    {
        const uint4* sh = (const uint4*)g_B1hi;
        const uint4* sl = (const uint4*)g_B1lo;
        uint4* dh = (uint4*)(smem + 65536);
        uint4* dl = (uint4*)(smem + 98304);
#pragma unroll
        for (int i = tid; i < 2048; i += 256) { dh[i] = sh[i]; dl[i] = sl[i]; }
    }

    {
        const int l = tid & 31;
        const int w = tid >> 5;
        uint2* Ah = (uint2*)smem;
        uint2* Al = (uint2*)(smem + 32768);
#pragma unroll
        for (int p = 0; p < 16; p++) {
            const int r = w + 8 * p;
            const int grow = block_row + r;
            float4 v = make_float4(0.f, 0.f, 0.f, 0.f);
            if (grow < n_nodes) v = *(const float4*)&x[(size_t)grow * IN_C + 4 * l];
            uint2 h, lo;
            split2(v.x, v.y, h.x, lo.x);
            split2(v.z, v.w, h.y, lo.y);
            const uint32_t off = ((uint32_t)r * 256u
                + ((uint32_t)((l >> 1) ^ (r & 7)) << 4) + (uint32_t)(l & 1) * 8u) >> 3;
            Ah[off] = h;
            Al[off] = lo;
        }
    }
    __syncthreads();

    gemm_compute_epilogue<HID_C, 8, false>(sA_hi, sA_lo, sB_hi, sB_lo,
                                           block_row, n_nodes, g_h1);
}

// === AGG1: a1 = relu(dinv[d]*(sum_in dinv[s]*h1[s] + dinv[d]*h1[d]) + b1) ===
__global__ __launch_bounds__(256) void agg1_kernel(const float* __restrict__ b1,
                                                   int n_nodes) {
    const int gid  = blockIdx.x * blockDim.x + threadIdx.x;
    const int node = gid >> 5;
    if (node >= n_nodes) return;
    const int lane = gid & 31;

    const int beg = g_rs[node];
    const int end = beg + g_cnt[node];
    const float dd = g_dinv[node];

    float4 self = *(const float4*)&g_h1[(size_t)node * HID_C + lane * 4];
    float4 acc, acc2;
    acc.x = dd * self.x; acc.y = dd * self.y;
    acc.z = dd * self.z; acc.w = dd * self.w;
    acc2 = make_float4(0.f, 0.f, 0.f, 0.f);

    int e = beg;
    for (; e + 1 < end; e += 2) {
        const int s0 = __ldg(&g_csr_src[e]);
        const int s1 = __ldg(&g_csr_src[e + 1]);
        const float d0 = __ldg(&g_dinv[s0]);
        const float d1 = __ldg(&g_dinv[s1]);
        const float4 v0 = *(const float4*)&g_h1[(size_t)s0 * HID_C + lane * 4];
        const float4 v1 = *(const float4*)&g_h1[(size_t)s1 * HID_C + lane * 4];
        acc.x  = fmaf(d0, v0.x, acc.x);  acc.y  = fmaf(d0, v0.y, acc.y);
        acc.z  = fmaf(d0, v0.z, acc.z);  acc.w  = fmaf(d0, v0.w, acc.w);
        acc2.x = fmaf(d1, v1.x, acc2.x); acc2.y = fmaf(d1, v1.y, acc2.y);
        acc2.z = fmaf(d1, v1.z, acc2.z); acc2.w = fmaf(d1, v1.w, acc2.w);
    }
    if (e < end) {
        const int s0 = __ldg(&g_csr_src[e]);
        const float d0 = __ldg(&g_dinv[s0]);
        const float4 v0 = *(const float4*)&g_h1[(size_t)s0 * HID_C + lane * 4];
        acc.x = fmaf(d0, v0.x, acc.x); acc.y = fmaf(d0, v0.y, acc.y);
        acc.z = fmaf(d0, v0.z, acc.z); acc.w = fmaf(d0, v0.w, acc.w);
    }
    acc.x += acc2.x; acc.y += acc2.y; acc.z += acc2.z; acc.w += acc2.w;

    const float4 b = *(const float4*)&b1[lane * 4];
    float4 o;
    o.x = fmaxf(dd * acc.x + b.x, 0.0f);
    o.y = fmaxf(dd * acc.y + b.y, 0.0f);
    o.z = fmaxf(dd * acc.z + b.z, 0.0f);
    o.w = fmaxf(dd * acc.w + b.w, 0.0f);
    *(float4*)&g_a1[(size_t)node * HID_C + lane * 4] = o;
}

// ===================== GEMM2: h2s = (a1@W2)*dinv (M_TILE=128) ===============
__global__ __launch_bounds__(256) void gemm2_kernel(int n_nodes) {
    extern __shared__ char smem[];
    const uint32_t sbase = smem_u32(smem);
    const uint32_t sA_hi = sbase;
    const uint32_t sA_lo = sbase + 32768;
    const uint32_t sB_hi = sbase + 65536;
    const uint32_t sB_lo = sbase + 81920;

    const int tid = threadIdx.x;
    const int block_row = blockIdx.x * 128;

    {
        const uint4* sh = (const uint4*)g_B2hi;
        const uint4* sl = (const uint4*)g_B2lo;
        uint4* dh = (uint4*)(smem + 65536);
        uint4* dl = (uint4*)(smem + 81920);
#pragma unroll
        for (int i = tid; i < 1024; i += 256) { dh[i] = sh[i]; dl[i] = sl[i]; }
    }

    {
        const int l = tid & 31;
        const int w = tid >> 5;
        uint2* Ah = (uint2*)smem;
        uint2* Al = (uint2*)(smem + 32768);
#pragma unroll
        for (int p = 0; p < 16; p++) {
            const int r = w + 8 * p;
            const int grow = block_row + r;
            float4 a = make_float4(0.f, 0.f, 0.f, 0.f);
            if (grow < n_nodes)
                a = *(const float4*)&g_a1[(size_t)grow * HID_C + 4 * l];
            uint2 h2, lo;
            split2(a.x, a.y, h2.x, lo.x);
            split2(a.z, a.w, h2.y, lo.y);
            const uint32_t off = ((uint32_t)r * 256u
                + ((uint32_t)((l >> 1) ^ (r & 7)) << 4) + (uint32_t)(l & 1) * 8u) >> 3;
            Ah[off] = h2;
            Al[off] = lo;
        }
    }
    __syncthreads();

    gemm_compute_epilogue<OUT_C, 4, true>(sA_hi, sA_lo, sB_hi, sB_lo,
                                          block_row, n_nodes, g_h2s);
}

// ===================== AGG2: out = dinv*(h2s[d] + sum_in h2s[s]) + b2 =======
__global__ __launch_bounds__(256) void agg2_kernel(const float* __restrict__ b2,
                                                   float* __restrict__ out,
                                                   int n_nodes) {
    const int gid  = blockIdx.x * blockDim.x + threadIdx.x;
    const int node = gid >> 4;
    if (node >= n_nodes) return;
    const int lane = gid & 15;

    const int beg = g_rs[node];
    const int end = beg + g_cnt[node];

    float4 acc = *(const float4*)&g_h2s[(size_t)node * OUT_C + lane * 4];  // self
    float4 acc2 = make_float4(0.f, 0.f, 0.f, 0.f);

    int e = beg;
    for (; e + 1 < end; e += 2) {
        const int s0 = __ldg(&g_csr_src[e]);
        const int s1 = __ldg(&g_csr_src[e + 1]);
        const float4 v0 = *(const float4*)&g_h2s[(size_t)s0 * OUT_C + lane * 4];
        const float4 v1 = *(const float4*)&g_h2s[(size_t)s1 * OUT_C + lane * 4];
        acc.x += v0.x; acc.y += v0.y; acc.z += v0.z; acc.w += v0.w;
        acc2.x += v1.x; acc2.y += v1.y; acc2.z += v1.z; acc2.w += v1.w;
    }
    if (e < end) {
        const int s0 = __ldg(&g_csr_src[e]);
        const float4 v0 = *(const float4*)&g_h2s[(size_t)s0 * OUT_C + lane * 4];
        acc.x += v0.x; acc.y += v0.y; acc.z += v0.z; acc.w += v0.w;
    }
    acc.x += acc2.x; acc.y += acc2.y; acc.z += acc2.z; acc.w += acc2.w;

    const float di = g_dinv[node];
    const float4 b = *(const float4*)&b2[lane * 4];
    float4 o;
    o.x = di * acc.x + b.x;
    o.y = di * acc.y + b.y;
    o.z = di * acc.z + b.z;
    o.w = di * acc.w + b.w;
    *(float4*)&out[(size_t)node * OUT_C + lane * 4] = o;
}

// ===================== launch ===============================================
extern "C" void kernel_launch(void* const* d_in, const int* in_sizes, int n_in,
                              void* d_out, int out_size) {
    const float* x   = (const float*)d_in[0];
    const float* W1  = (const float*)d_in[1];
    const float* b1  = (const float*)d_in[2];
    const float* W2  = (const float*)d_in[3];
    const float* b2  = (const float*)d_in[4];
    const int*   src = (const int*)  d_in[5];
    const int*   dst = (const int*)  d_in[6];
    float*       out = (float*)d_out;

    const int n = in_sizes[0] / IN_C;   // 100000
    const int E = in_sizes[5];          // 600000

    static cudaStream_t s2 = nullptr;
    static cudaEvent_t ev_fork = nullptr, ev_csr = nullptr;
    static bool init_done = false;
    if (!init_done) {
        cudaFuncSetAttribute(gemm1_kernel,
                             cudaFuncAttributeMaxDynamicSharedMemorySize, 131072);
        cudaFuncSetAttribute(gemm2_kernel,
                             cudaFuncAttributeMaxDynamicSharedMemorySize, 98304);
        cudaStreamCreateWithFlags(&s2, cudaStreamNonBlocking);
        cudaEventCreateWithFlags(&ev_fork, cudaEventDisableTiming);
        cudaEventCreateWithFlags(&ev_csr, cudaEventDisableTiming);
        init_done = true;
    }

    // ---- fork: CSR build on side stream, concurrent with prep_w + gemm1 ----
    cudaEventRecord(ev_fork, 0);
    cudaStreamWaitEvent(s2, ev_fork, 0);

    // side stream: zero -> count -> scan1(+dinv) -> scan3 -> fill
    zero_kernel <<<(n + 255) / 256, 256, 0, s2>>>(n);
    count_kernel<<<(E + 255) / 256, 256, 0, s2>>>(dst, E);
    scan1_kernel<<<SCAN_NB, SCAN_BLK, 0, s2>>>(n);
    scan3_kernel<<<SCAN_NB, SCAN_BLK, 0, s2>>>(n);
    fill_kernel <<<(E + 255) / 256, 256, 0, s2>>>(src, dst, E);
    cudaEventRecord(ev_csr, s2);

    // main stream: weight prep + gemm1 (no CSR/dinv dependency)
    prep_w_kernel<<<(IN_C * HID_C + HID_C * OUT_C + 255) / 256, 256>>>(W1, W2);
    const int tiles = (n + 127) / 128;
    gemm1_kernel<<<tiles, 256, 131072>>>(x, n);

    // join: agg1 needs CSR + dinv
    cudaStreamWaitEvent(0, ev_csr, 0);
    {
        long long threads = (long long)n * 32;
        agg1_kernel<<<(int)((threads + 255) / 256), 256>>>(b1, n);
    }

    // layer 2
    gemm2_kernel<<<tiles, 256, 98304>>>(n);
    {
        long long threads = (long long)n * 16;
        agg2_kernel<<<(int)((threads + 255) / 256), 256>>>(b2, out, n);
    }
}